// round 15
// baseline (speedup 1.0000x reference)
#include <cuda_runtime.h>
#include <cstdint>

// Router: logits = x[8192,4096] @ kernel[4096,64]; top-8 per token; softmax over top-8.
// out (fp32): [0 .. T*8) = weights, [T*8 .. 2*T*8) = expert indices (as float)
//
// Physical split-K(8): pass1 computes per-slab partials (sequential fp32, ascending kk
// within each 512-K slab); pass2 folds partials in ascending slab order, then
// top-8 + softmax. Accumulation order replicates the reference — DO NOT CHANGE.
//
// Scratch layout element-major [t][e][slab]: the 8 slab partials of one (t,e) are
// 32 contiguous bytes -> pass2 folds in registers, no smem, no barriers.

#define T_TOK 8192
#define D_DIM 4096
#define E_EXP 64
#define NSLAB 8
#define SLABK 512
#define TT    32      // tokens per pass1 CTA
#define KC    32      // K-chunk per stage
#define LDK   72      // k-tile row stride (floats), phase-split (conflict-free)
#define XTILE (TT * KC)          // 1024 floats
#define KTILE (KC * LDK)         // 2304 floats
#define STAGE (XTILE + KTILE)    // 3328 floats = 13.3 KB

#define TT2   8       // tokens per pass2 CTA (one warp per token)

typedef unsigned long long u64;

__device__ float g_partial[(size_t)T_TOK * E_EXP * NSLAB];   // [t][e][slab], 16.8 MB

__device__ __forceinline__ u64 ffma2(u64 a, u64 b, u64 c) {
    u64 d;
    asm("fma.rn.f32x2 %0, %1, %2, %3;" : "=l"(d) : "l"(a), "l"(b), "l"(c));
    return d;
}
__device__ __forceinline__ u64 bcast2(float x) {
    u64 r;
    asm("mov.b64 %0, {%1, %1};" : "=l"(r) : "f"(x));
    return r;
}
__device__ __forceinline__ void cp16(uint32_t smem_addr, const void* gptr) {
    asm volatile("cp.async.cg.shared.global [%0], [%1], 16;" :: "r"(smem_addr), "l"(gptr));
}
__device__ __forceinline__ void cp_commit() { asm volatile("cp.async.commit_group;"); }
__device__ __forceinline__ void cp_wait0()  { asm volatile("cp.async.wait_group 0;"); }

// ============================ PASS 1: slab GEMM ============================
// grid (256 t-blocks, 8 slabs) = 2048 CTAs, 64 threads, 8 CTAs/SM.
// Thread tile: 4 rows x 8 experts. (Compute/pipeline identical to R13/R14.)
__global__ __launch_bounds__(64, 8) void slab_gemm_kernel(
    const float* __restrict__ x,
    const float* __restrict__ ker)
{
    __shared__ float sm[2 * STAGE];   // 26.6 KB

    const int tid  = threadIdx.x;
    const int tx   = tid & 7;            // e-group: e0 = tx*8
    const int ty   = tid >> 3;           // 0..7 -> rows ty + 8*i (i=0..3)
    const int e0   = tx * 8;
    const int koff = e0 + ((tx >= 4) ? 4 : 0);
    const int tb   = blockIdx.x * TT;
    const int k0   = blockIdx.y * SLABK;

    const uint32_t smb = (uint32_t)__cvta_generic_to_shared(sm);

    u64 acc[4][4];
#pragma unroll
    for (int i = 0; i < 4; i++)
#pragma unroll
        for (int j = 0; j < 4; j++) acc[i][j] = 0ull;

    auto load_chunk = [&](int c) {
        uint32_t base = smb + (uint32_t)((c & 1) * STAGE) * 4u;
        // x: 32 rows x 32 fl = 256 float4 / 64 thr = 4 each
#pragma unroll
        for (int j = 0; j < 4; j++) {
            int f  = j * 64 + tid;
            int d4 = f & 7;                           // chunk within row (8 per row)
            int t  = f >> 3;                          // 0..31
            uint32_t dst = base + (uint32_t)(t * KC + ((d4 ^ (t & 7)) << 2)) * 4u;
            const float* src = x + (size_t)(tb + t) * D_DIM + k0 + c * KC + d4 * 4;
            cp16(dst, src);
        }
        // k: 32 kk x 64 e = 512 float4 / 64 thr = 8 each (phase-split rows)
        {
            int e4 = tid & 15;
            int ofs = e4 * 4 + ((e4 >= 8) ? 4 : 0);
#pragma unroll
            for (int j = 0; j < 8; j++) {
                int dk = 4 * j + (tid >> 4);
                uint32_t dst = base + (uint32_t)(XTILE + dk * LDK + ofs) * 4u;
                const float* src = ker + (size_t)(k0 + c * KC + dk) * E_EXP + e4 * 4;
                cp16(dst, src);
            }
        }
        cp_commit();
    };

    load_chunk(0);

    const int nChunks = SLABK / KC;   // 16
    for (int c = 0; c < nChunks; c++) {
        cp_wait0();                   // load(c) complete (issued last iter; overlapped)
        __syncthreads();              // data visible; prior readers of buffer (c&1) done

        if (c + 1 < nChunks) load_chunk(c + 1);

        const int b = c & 1;
        const float* xb_ = sm + b * STAGE;
        const float* kb_ = sm + b * STAGE + XTILE;

#pragma unroll
        for (int c4 = 0; c4 < KC / 4; c4++) {
            const int ch = ((c4 ^ ty) << 2);
            float4 xv[4];
#pragma unroll
            for (int i = 0; i < 4; i++)
                xv[i] = *reinterpret_cast<const float4*>(xb_ + (ty + 8 * i) * KC + ch);
#pragma unroll
            for (int q = 0; q < 4; q++) {
                const int kk = c4 * 4 + q;
                ulonglong2 ka = *reinterpret_cast<const ulonglong2*>(kb_ + kk * LDK + koff);
                ulonglong2 kc = *reinterpret_cast<const ulonglong2*>(kb_ + kk * LDK + koff + 4);
#pragma unroll
                for (int i = 0; i < 4; i++) {
                    float fx = (q == 0) ? xv[i].x : (q == 1) ? xv[i].y
                             : (q == 2) ? xv[i].z : xv[i].w;
                    u64 xp = bcast2(fx);
                    acc[i][0] = ffma2(xp, ka.x, acc[i][0]);
                    acc[i][1] = ffma2(xp, ka.y, acc[i][1]);
                    acc[i][2] = ffma2(xp, kc.x, acc[i][2]);
                    acc[i][3] = ffma2(xp, kc.y, acc[i][3]);
                }
            }
        }
    }

    // write slab partials, element-major layout [t][e][slab]
    const int slab = blockIdx.y;
#pragma unroll
    for (int i = 0; i < 4; i++) {
        int t = tb + ty + 8 * i;
        float* base = g_partial + ((size_t)t * E_EXP) * NSLAB + slab;
        const float* a = reinterpret_cast<const float*>(&acc[i][0]);   // e0..e7
#pragma unroll
        for (int j = 0; j < 8; j++)
            base[(size_t)(e0 + j) * NSLAB] = a[j];
    }
}

// ====================== PASS 2: fold + top-8 + softmax ======================
// grid = 1024 (8 tokens per CTA), 256 threads = 8 warps, one warp per token.
// No smem, no barriers: each lane loads elements lane & lane+32 (8 contiguous
// slab values each), folds sequentially in ascending slab order, then butterfly
// top-8 + softmax.
__global__ __launch_bounds__(256) void fold_topk_kernel(
    float* __restrict__ out,
    int half)
{
    const int w    = threadIdx.x >> 5;
    const int lane = threadIdx.x & 31;
    const unsigned FULL = 0xffffffffu;

    const int t = blockIdx.x * TT2 + w;
    const float* p = g_partial + (size_t)t * E_EXP * NSLAB;

    // element `lane`: slabs 0..7 contiguous
    float4 a0 = *reinterpret_cast<const float4*>(p + (size_t)lane * NSLAB);
    float4 a1 = *reinterpret_cast<const float4*>(p + (size_t)lane * NSLAB + 4);
    // element `lane+32`
    float4 b0 = *reinterpret_cast<const float4*>(p + (size_t)(lane + 32) * NSLAB);
    float4 b1 = *reinterpret_cast<const float4*>(p + (size_t)(lane + 32) * NSLAB + 4);

    // sequential fold, ascending slab order (bit-exact association)
    float v0 = a0.x;
    v0 = v0 + a0.y; v0 = v0 + a0.z; v0 = v0 + a0.w;
    v0 = v0 + a1.x; v0 = v0 + a1.y; v0 = v0 + a1.z; v0 = v0 + a1.w;
    float v1 = b0.x;
    v1 = v1 + b0.y; v1 = v1 + b0.z; v1 = v1 + b0.w;
    v1 = v1 + b1.x; v1 = v1 + b1.y; v1 = v1 + b1.z; v1 = v1 + b1.w;

    float vals[8];
    int   inds[8];
#pragma unroll
    for (int k = 0; k < 8; k++) {
        float bv; int bi;
        if (v0 >= v1) { bv = v0; bi = lane; }
        else          { bv = v1; bi = lane + 32; }
#pragma unroll
        for (int off = 16; off > 0; off >>= 1) {
            float ov = __shfl_xor_sync(FULL, bv, off);
            int   oi = __shfl_xor_sync(FULL, bi, off);
            if (ov > bv || (ov == bv && oi < bi)) { bv = ov; bi = oi; }
        }
        vals[k] = bv;
        inds[k] = bi;
        if (bi == lane)           v0 = -3.4e38f;
        else if (bi == lane + 32) v1 = -3.4e38f;
    }

    if (lane == 0) {
        float m = vals[0];
        float ws[8];
        float ssum = 0.0f;
#pragma unroll
        for (int k = 0; k < 8; k++) { ws[k] = expf(vals[k] - m); ssum += ws[k]; }
        float r = 1.0f / ssum;
#pragma unroll
        for (int k = 0; k < 8; k++) {
            out[t * 8 + k]        = ws[k] * r;
            out[half + t * 8 + k] = (float)inds[k];
        }
    }
}

extern "C" void kernel_launch(void* const* d_in, const int* in_sizes, int n_in,
                              void* d_out, int out_size) {
    const float* x   = (const float*)d_in[0];
    const float* ker = (const float*)d_in[1];
    float* out = (float*)d_out;
    int half = out_size / 2;

    dim3 grid1(T_TOK / TT, NSLAB);
    slab_gemm_kernel<<<grid1, 64>>>(x, ker);
    fold_topk_kernel<<<T_TOK / TT2, 256>>>(out, half);
}